// round 1
// baseline (speedup 1.0000x reference)
#include <cuda_runtime.h>
#include <cstdint>

// Problem constants
#define B_    4
#define L_    1024
#define FP_   32
#define DP_   8
#define F_    32
#define D_    16
#define K_    3
#define W_    1022            // L - K + 1
#define N_    96              // K * FP
#define WB_   4088            // W * B
#define COLS_ 512             // F * D
#define UH_PER_WB 49152       // N * COLS
#define ITERS_ 3

// Global scratch for u_hat: 4088 * 49152 floats = 803.7 MB (allowed: __device__ global)
__device__ float g_uhat[(size_t)WB_ * UH_PER_WB];

// ---------------------------------------------------------------------------
// Phase 1: u_hat[wb, n, col] = bias[n,col] + sum_d x[b, w+k, fp, d] * W[n, f, d, e]
//   col = f*16 + e.  Grid: (n=96, tile=32), 256 threads. Each thread owns 2
//   adjacent cols (2t, 2t+1) and iterates 128 wb-rows in pairs using
//   fma.rn.f32x2 (packed rows in one 64-bit reg).
// ---------------------------------------------------------------------------
__global__ __launch_bounds__(256) void uhat_kernel(const float* __restrict__ x,
                                                   const float* __restrict__ wgt,
                                                   const float* __restrict__ bias)
{
    const int n    = blockIdx.x;      // 0..95
    const int tile = blockIdx.y;      // 0..31
    const int t    = threadIdx.x;
    const int k    = n >> 5;          // n / FP
    const int fp   = n & 31;          // n % FP

    __shared__ float xsT[DP_][128];   // transposed: xsT[d][r], rowpairs are 8B-contiguous

    // Stage x rows for this tile (wb = tile*128 + r)
    {
        int r = t >> 1, q = t & 1;
        int wb = tile * 128 + r;
        float4 v = make_float4(0.f, 0.f, 0.f, 0.f);
        if (wb < WB_) {
            int w = wb >> 2, b = wb & 3;
            const float* p = x + ((size_t)b * (L_ * FP_ * DP_)
                                  + (size_t)(w + k) * (FP_ * DP_)
                                  + fp * DP_ + q * 4);
            v = *(const float4*)p;
        }
        xsT[q * 4 + 0][r] = v.x;
        xsT[q * 4 + 1][r] = v.y;
        xsT[q * 4 + 2][r] = v.z;
        xsT[q * 4 + 3][r] = v.w;
    }

    // Load weight for my 2 cols, duplicated into both halves of a 64-bit reg
    const int c0 = 2 * t;             // even col
    const int f  = c0 >> 4;
    const int e0 = c0 & 15;           // even
    unsigned long long wd0[DP_], wd1[DP_];
    const float* wp = wgt + (size_t)n * (F_ * DP_ * D_) + f * (DP_ * D_) + e0;
#pragma unroll
    for (int d = 0; d < DP_; d++) {
        float2 w2 = *(const float2*)(wp + d * D_);
        asm("mov.b64 %0, {%1, %1};" : "=l"(wd0[d]) : "f"(w2.x));
        asm("mov.b64 %0, {%1, %1};" : "=l"(wd1[d]) : "f"(w2.y));
    }
    float2 bz = *(const float2*)(bias + (size_t)n * COLS_ + c0);
    unsigned long long bia, bib;
    asm("mov.b64 %0, {%1, %1};" : "=l"(bia) : "f"(bz.x));
    asm("mov.b64 %0, {%1, %1};" : "=l"(bib) : "f"(bz.y));

    __syncthreads();

    const int wb0 = tile * 128;
#pragma unroll 1
    for (int r = 0; r < 128; r += 2) {
        unsigned long long acc0 = bia, acc1 = bib;
#pragma unroll
        for (int d = 0; d < DP_; d++) {
            unsigned long long xp = *(const unsigned long long*)&xsT[d][r];  // (x[r][d], x[r+1][d])
            asm("fma.rn.f32x2 %0, %1, %2, %0;" : "+l"(acc0) : "l"(xp), "l"(wd0[d]));
            asm("fma.rn.f32x2 %0, %1, %2, %0;" : "+l"(acc1) : "l"(xp), "l"(wd1[d]));
        }
        float lo0, hi0, lo1, hi1;
        asm("mov.b64 {%0, %1}, %2;" : "=f"(lo0), "=f"(hi0) : "l"(acc0));
        asm("mov.b64 {%0, %1}, %2;" : "=f"(lo1), "=f"(hi1) : "l"(acc1));
        int wbA = wb0 + r, wbB = wb0 + r + 1;
        if (wbA < WB_)
            *(float2*)&g_uhat[(size_t)wbA * UH_PER_WB + (size_t)n * COLS_ + c0] = make_float2(lo0, lo1);
        if (wbB < WB_)
            *(float2*)&g_uhat[(size_t)wbB * UH_PER_WB + (size_t)n * COLS_ + c0] = make_float2(hi0, hi1);
    }
}

// ---------------------------------------------------------------------------
// Phase 2: dynamic routing. One CTA per wb (4088 CTAs), 256 threads.
//   u_hat tile (196 KB) staged once into dynamic smem; iteration-0 's' is
//   accumulated during the load (c uniform = 1/32 at b=0).
// Shared layout (floats):
//   su[49152] | sb[96*33] | sc[96*33] | sv[512] | spart[1024] | sscale[32]
//   total = 57056 floats = 228224 B
// ---------------------------------------------------------------------------
#define SB_PITCH 33
#define SMEM_FLOATS (UH_PER_WB + 2 * (N_ * SB_PITCH) + 512 + 1024 + 32)

__global__ __launch_bounds__(256) void routing_kernel(float* __restrict__ out)
{
    extern __shared__ float smem[];
    float* su     = smem;                       // 49152
    float* sb     = su + UH_PER_WB;             // 3168 (b logits, pitch 33)
    float* sc     = sb + N_ * SB_PITCH;         // 3168 (coupling coeffs)
    float* sv     = sc + N_ * SB_PITCH;         // 512  (s then v, in place)
    float* spart  = sv + 512;                   // 1024 (per-thread partial s)
    float* sscale = spart + 1024;               // 32

    const int wb = blockIdx.x;
    const int t  = threadIdx.x;
    const float* g = g_uhat + (size_t)wb * UH_PER_WB;

    // zero b logits
    for (int i = t; i < N_ * SB_PITCH; i += 256) sb[i] = 0.f;

    // Load u_hat into smem + fused iter-0 partial s.
    // float4 index j = t + 256*i: col4 = j%128 = t%128 (fixed), n = t/128 + 2i.
    float4 acc = make_float4(0.f, 0.f, 0.f, 0.f);
#pragma unroll 4
    for (int i = 0; i < 48; i++) {
        int j = t + 256 * i;
        float4 v = *(const float4*)(g + 4 * j);
        ((float4*)su)[j] = v;
        acc.x += v.x; acc.y += v.y; acc.z += v.z; acc.w += v.w;
    }
    ((float4*)spart)[t] = acc;
    __syncthreads();

    if (t < 128) {
        float4 a = ((float4*)spart)[t];
        float4 b2 = ((float4*)spart)[t + 128];
        const float inv = 1.f / 32.f;
        float4 s4 = make_float4((a.x + b2.x) * inv, (a.y + b2.y) * inv,
                                (a.z + b2.z) * inv, (a.w + b2.w) * inv);
        ((float4*)sv)[t] = s4;
    }
    __syncthreads();

    for (int it = 0; it < ITERS_; it++) {
        if (it > 0) {
            // softmax over f per n: sc[n][f] = softmax(sb[n][:])
            if (t < N_) {
                float mx = -1e30f;
#pragma unroll
                for (int f2 = 0; f2 < 32; f2++) mx = fmaxf(mx, sb[t * SB_PITCH + f2]);
                float ex[32];
                float ssum = 0.f;
#pragma unroll
                for (int f2 = 0; f2 < 32; f2++) {
                    float e = __expf(sb[t * SB_PITCH + f2] - mx);
                    ex[f2] = e; ssum += e;
                }
                float inv = 1.f / ssum;
#pragma unroll
                for (int f2 = 0; f2 < 32; f2++) sc[t * SB_PITCH + f2] = ex[f2] * inv;
            }
            __syncthreads();

            // s[col] = sum_n c[n,f] * u_hat[n,col]
            if (t < 128) {
                int f = t >> 2;
                float4 s4 = make_float4(0.f, 0.f, 0.f, 0.f);
                const float4* up = (const float4*)su + t;
#pragma unroll 4
                for (int nn = 0; nn < N_; nn++) {
                    float c = sc[nn * SB_PITCH + f];
                    float4 u = up[nn * 128];
                    s4.x += c * u.x; s4.y += c * u.y; s4.z += c * u.z; s4.w += c * u.w;
                }
                ((float4*)sv)[t] = s4;
            }
            __syncthreads();
        }

        // squash: per f, scale = |s|^2/(1+|s|^2) / |s|
        if (t < 32) {
            float sq = 0.f;
            const float4* vp = (const float4*)sv + t * 4;
#pragma unroll
            for (int i = 0; i < 4; i++) {
                float4 a = vp[i];
                sq += a.x * a.x + a.y * a.y + a.z * a.z + a.w * a.w;
            }
            sq = fmaxf(sq, 1e-30f);
            float r = rsqrtf(sq);
            sscale[t] = sq / (1.f + sq) * r;
        }
        __syncthreads();
        if (t < 128) {
            float s = sscale[t >> 2];
            float4 a = ((float4*)sv)[t];
            a.x *= s; a.y *= s; a.z *= s; a.w *= s;
            ((float4*)sv)[t] = a;
        }
        __syncthreads();

        if (it < ITERS_ - 1) {
            // b[n,f] += sum_e v[f,e] * u_hat[n,f,e]
            // lane l: e4 = l&3, f = (warp%4)*8 + (l>>2); warp/4 picks n half.
            int l = t & 31, wrp = t >> 5;
            int e4 = l & 3;
            int f  = (wrp & 3) * 8 + (l >> 2);
            int nbeg = (wrp >> 2) * 48;
            float4 v4 = ((float4*)sv)[f * 4 + e4];
#pragma unroll 4
            for (int nn = nbeg; nn < nbeg + 48; nn++) {
                float4 u = ((const float4*)su)[nn * 128 + f * 4 + e4];
                float p = v4.x * u.x + v4.y * u.y + v4.z * u.z + v4.w * u.w;
                p += __shfl_down_sync(0xffffffffu, p, 2);
                p += __shfl_down_sync(0xffffffffu, p, 1);
                if (e4 == 0) sb[nn * SB_PITCH + f] += p;
            }
            __syncthreads();
        }
    }

    // out[b, w, f, e] = v
    if (t < 128) {
        int w = wb >> 2, b = wb & 3;
        ((float4*)(out + (size_t)b * (W_ * COLS_) + (size_t)w * COLS_))[t] = ((float4*)sv)[t];
    }
}

// ---------------------------------------------------------------------------
extern "C" void kernel_launch(void* const* d_in, const int* in_sizes, int n_in,
                              void* d_out, int out_size)
{
    const float* x    = (const float*)d_in[0];
    const float* wgt  = (const float*)d_in[1];
    const float* bias = (const float*)d_in[2];
    float* out = (float*)d_out;

    const int smem_bytes = SMEM_FLOATS * (int)sizeof(float);  // 228224
    cudaFuncSetAttribute(routing_kernel,
                         cudaFuncAttributeMaxDynamicSharedMemorySize, smem_bytes);

    dim3 g1(N_, 32);
    uhat_kernel<<<g1, 256>>>(x, wgt, bias);
    routing_kernel<<<WB_, 256, smem_bytes>>>(out);
}

// round 3
// speedup vs baseline: 1.7197x; 1.7197x over previous
#include <cuda_runtime.h>
#include <cuda_fp16.h>
#include <cstdint>

// Problem constants
#define B_    4
#define L_    1024
#define FP_   32
#define DP_   8
#define F_    32
#define D_    16
#define K_    3
#define W_    1022            // L - K + 1
#define N_    96              // K * FP
#define WB_   4088            // W * B
#define COLS_ 512             // F * D
#define UH_PER_WB 49152       // N * COLS
#define ITERS_ 3
#define GRID_ 148             // persistent CTAs (B200: 148 SMs)

// Global scratch for u_hat in fp16: 4088 * 49152 * 2B = 401.8 MB
__device__ __half g_uhat[(size_t)WB_ * UH_PER_WB];

// ---------------------------------------------------------------------------
// Phase 1: u_hat[wb, n, col] = bias[n,col] + sum_d x[b,w+k,fp,d] * W[n,f,d,e]
// Grid (n=96, tile=32), 256 threads; 2 cols/thread, row-pairs via fma.rn.f32x2.
// Output stored fp16.
// ---------------------------------------------------------------------------
__global__ __launch_bounds__(256) void uhat_kernel(const float* __restrict__ x,
                                                   const float* __restrict__ wgt,
                                                   const float* __restrict__ bias)
{
    const int n    = blockIdx.x;      // 0..95
    const int tile = blockIdx.y;      // 0..31
    const int t    = threadIdx.x;
    const int k    = n >> 5;
    const int fp   = n & 31;

    __shared__ float xsT[DP_][128];   // transposed: xsT[d][r]

    {
        int r = t >> 1, q = t & 1;
        int wb = tile * 128 + r;
        float4 v = make_float4(0.f, 0.f, 0.f, 0.f);
        if (wb < WB_) {
            int w = wb >> 2, b = wb & 3;
            const float* p = x + ((size_t)b * (L_ * FP_ * DP_)
                                  + (size_t)(w + k) * (FP_ * DP_)
                                  + fp * DP_ + q * 4);
            v = *(const float4*)p;
        }
        xsT[q * 4 + 0][r] = v.x;
        xsT[q * 4 + 1][r] = v.y;
        xsT[q * 4 + 2][r] = v.z;
        xsT[q * 4 + 3][r] = v.w;
    }

    const int c0 = 2 * t;
    const int f  = c0 >> 4;
    const int e0 = c0 & 15;
    unsigned long long wd0[DP_], wd1[DP_];
    const float* wp = wgt + (size_t)n * (F_ * DP_ * D_) + f * (DP_ * D_) + e0;
#pragma unroll
    for (int d = 0; d < DP_; d++) {
        float2 w2 = *(const float2*)(wp + d * D_);
        asm("mov.b64 %0, {%1, %1};" : "=l"(wd0[d]) : "f"(w2.x));
        asm("mov.b64 %0, {%1, %1};" : "=l"(wd1[d]) : "f"(w2.y));
    }
    float2 bz = *(const float2*)(bias + (size_t)n * COLS_ + c0);
    unsigned long long bia, bib;
    asm("mov.b64 %0, {%1, %1};" : "=l"(bia) : "f"(bz.x));
    asm("mov.b64 %0, {%1, %1};" : "=l"(bib) : "f"(bz.y));

    __syncthreads();

    const int wb0 = tile * 128;
#pragma unroll 1
    for (int r = 0; r < 128; r += 2) {
        unsigned long long acc0 = bia, acc1 = bib;
#pragma unroll
        for (int d = 0; d < DP_; d++) {
            unsigned long long xp = *(const unsigned long long*)&xsT[d][r];
            asm("fma.rn.f32x2 %0, %1, %2, %0;" : "+l"(acc0) : "l"(xp), "l"(wd0[d]));
            asm("fma.rn.f32x2 %0, %1, %2, %0;" : "+l"(acc1) : "l"(xp), "l"(wd1[d]));
        }
        float lo0, hi0, lo1, hi1;
        asm("mov.b64 {%0, %1}, %2;" : "=f"(lo0), "=f"(hi0) : "l"(acc0));
        asm("mov.b64 {%0, %1}, %2;" : "=f"(lo1), "=f"(hi1) : "l"(acc1));
        int wbA = wb0 + r, wbB = wb0 + r + 1;
        if (wbA < WB_)
            *(__half2*)&g_uhat[(size_t)wbA * UH_PER_WB + (size_t)n * COLS_ + c0]
                = __floats2half2_rn(lo0, lo1);
        if (wbB < WB_)
            *(__half2*)&g_uhat[(size_t)wbB * UH_PER_WB + (size_t)n * COLS_ + c0]
                = __floats2half2_rn(hi0, hi1);
    }
}

// ---------------------------------------------------------------------------
// Phase 2: persistent routing. 148 CTAs x 512 threads; each CTA loops over
// wb tiles, double-buffering the 96KB fp16 u_hat tile via cp.async.
// smem layout (bytes):
//   su0[98304] | su1[98304] | sb fp32[96*32]=12288 | sc fp16[96*32]=6144
//   | sv fp32[512]=2048 | sp fp32[1024]=4096 | ss fp32[32]=128   => 221312 B
// ---------------------------------------------------------------------------
#define SU_BYTES 98304
#define OFF_SU0  0
#define OFF_SU1  98304
#define OFF_SB   196608
#define OFF_SC   208896
#define OFF_SV   215040
#define OFF_SP   217088
#define OFF_SS   221184
#define SMEM_TOTAL 221312

// 512 threads x 16B x LOAD_ITERS = 98304 bytes per tile
#define LOAD_ITERS 12

__global__ __launch_bounds__(512, 1) void routing_kernel(float* __restrict__ out)
{
    extern __shared__ __align__(16) unsigned char smem[];
    float*  sb = (float*)(smem + OFF_SB);
    __half* sc = (__half*)(smem + OFF_SC);
    float*  sv = (float*)(smem + OFF_SV);
    float*  sp = (float*)(smem + OFF_SP);
    float*  ss = (float*)(smem + OFF_SS);

    const int t   = threadIdx.x;
    const int bid = blockIdx.x;
    const uint32_t smem_u32 = (uint32_t)__cvta_generic_to_shared(smem);

    // issue cp.async loads for one tile: 12 x (512 threads x 16B) = 98304 B
    auto issue_load = [&](int wb, int bufsel) {
        const char* src = (const char*)(g_uhat + (size_t)wb * UH_PER_WB) + t * 16;
        uint32_t dst = smem_u32 + (bufsel ? OFF_SU1 : OFF_SU0) + t * 16;
#pragma unroll
        for (int i = 0; i < LOAD_ITERS; i++) {
            asm volatile("cp.async.cg.shared.global [%0], [%1], 16;"
                         :: "r"(dst + i * 8192), "l"(src + (size_t)i * 8192));
        }
        asm volatile("cp.async.commit_group;");
    };

    issue_load(bid, 0);
    int buf = 0;

    for (int wb = bid; wb < WB_; wb += GRID_) {
        const int nxt = wb + GRID_;
        if (nxt < WB_) {
            issue_load(nxt, buf ^ 1);
            asm volatile("cp.async.wait_group 1;" ::: "memory");
        } else {
            asm volatile("cp.async.wait_group 0;" ::: "memory");
        }
        // zero b logits (96*32 = 3072 floats)
#pragma unroll
        for (int i = 0; i < 6; i++) sb[t + 512 * i] = 0.f;
        __syncthreads();

        const __half2* su2 = (const __half2*)(smem + (buf ? OFF_SU1 : OFF_SU0));
        const __half*  suh = (const __half*)(smem + (buf ? OFF_SU1 : OFF_SU0));

        const int c2   = t & 255;     // col pair (2*c2, 2*c2+1)
        const int hsel = t >> 8;      // n-range half
        const int fA   = c2 >> 3;     // f for my col pair
        const int nbeg = hsel * 48;

        for (int it = 0; it < ITERS_; it++) {
            // ---- Pass A: s[col] = sum_n c[n,f] * u[n,col] (512 threads, n split 2-way)
            float ax = 0.f, ay = 0.f;
            if (it == 0) {
#pragma unroll 4
                for (int nn = nbeg; nn < nbeg + 48; nn++) {
                    float2 u = __half22float2(su2[nn * 256 + c2]);
                    ax += u.x; ay += u.y;
                }
            } else {
#pragma unroll 4
                for (int nn = nbeg; nn < nbeg + 48; nn++) {
                    float c = __half2float(sc[nn * 32 + fA]);
                    float2 u = __half22float2(su2[nn * 256 + c2]);
                    ax = fmaf(c, u.x, ax);
                    ay = fmaf(c, u.y, ay);
                }
            }
            ((float2*)sp)[t] = make_float2(ax, ay);
            __syncthreads();
            if (t < 256) {
                float2 a  = ((float2*)sp)[t];
                float2 b2 = ((float2*)sp)[t + 256];
                float sx = a.x + b2.x, sy = a.y + b2.y;
                if (it == 0) { sx *= (1.f / 32.f); sy *= (1.f / 32.f); }
                ((float2*)sv)[t] = make_float2(sx, sy);
            }
            __syncthreads();

            // ---- squash
            if (t < 32) {
                float sq = 0.f;
                const float4* vp = (const float4*)sv + t * 4;
#pragma unroll
                for (int i = 0; i < 4; i++) {
                    float4 a = vp[i];
                    sq += a.x * a.x + a.y * a.y + a.z * a.z + a.w * a.w;
                }
                sq = fmaxf(sq, 1e-30f);
                ss[t] = sq / (1.f + sq) * rsqrtf(sq);
            }
            __syncthreads();
            if (t < 128) {
                float s = ss[t >> 2];
                float4 a = ((float4*)sv)[t];
                a.x *= s; a.y *= s; a.z *= s; a.w *= s;
                ((float4*)sv)[t] = a;
            }
            __syncthreads();

            if (it < ITERS_ - 1) {
                // ---- Pass D: b[n,f] += sum_e v[f,e]*u[n,f,e]
                {
                    int l  = t & 31, w8 = t >> 5;
                    int e4 = l & 3;
                    int f  = (w8 & 3) * 8 + (l >> 2);
                    int n0 = (w8 >> 2) * 24;
                    float4 v4 = ((const float4*)sv)[f * 4 + e4];
#pragma unroll 4
                    for (int nn = n0; nn < n0 + 24; nn++) {
                        uint2 raw = *(const uint2*)(suh + nn * 512 + f * 16 + e4 * 4);
                        float2 u0 = __half22float2(*(__half2*)&raw.x);
                        float2 u1 = __half22float2(*(__half2*)&raw.y);
                        float p = v4.x * u0.x + v4.y * u0.y + v4.z * u1.x + v4.w * u1.y;
                        p += __shfl_down_sync(0xffffffffu, p, 2);
                        p += __shfl_down_sync(0xffffffffu, p, 1);
                        if (e4 == 0) sb[nn * 32 + f] += p;
                    }
                }
                __syncthreads();
                // ---- Pass C: softmax over f per n -> sc (warp per 6 rows)
                {
                    int wrp = t >> 5, lane = t & 31;
#pragma unroll
                    for (int q = 0; q < 6; q++) {
                        int n = wrp * 6 + q;
                        float b = sb[n * 32 + lane];
                        float mx = b;
#pragma unroll
                        for (int o = 16; o > 0; o >>= 1)
                            mx = fmaxf(mx, __shfl_xor_sync(0xffffffffu, mx, o));
                        float e = __expf(b - mx);
                        float z = e;
#pragma unroll
                        for (int o = 16; o > 0; o >>= 1)
                            z += __shfl_xor_sync(0xffffffffu, z, o);
                        sc[n * 32 + lane] = __float2half(e / z);
                    }
                }
                __syncthreads();
            }
        }

        // ---- output: out[b, w, f, e]
        if (t < 128) {
            int w = wb >> 2, b = wb & 3;
            ((float4*)(out + (size_t)b * (W_ * COLS_) + (size_t)w * COLS_))[t]
                = ((float4*)sv)[t];
        }
        __syncthreads();
        buf ^= 1;
    }
}

// ---------------------------------------------------------------------------
extern "C" void kernel_launch(void* const* d_in, const int* in_sizes, int n_in,
                              void* d_out, int out_size)
{
    const float* x    = (const float*)d_in[0];
    const float* wgt  = (const float*)d_in[1];
    const float* bias = (const float*)d_in[2];
    float* out = (float*)d_out;

    cudaFuncSetAttribute(routing_kernel,
                         cudaFuncAttributeMaxDynamicSharedMemorySize, SMEM_TOTAL);

    dim3 g1(N_, 32);
    uhat_kernel<<<g1, 256>>>(x, wgt, bias);
    routing_kernel<<<GRID_, 512, SMEM_TOTAL>>>(out);
}

// round 4
// speedup vs baseline: 2.0354x; 1.1835x over previous
#include <cuda_runtime.h>
#include <cuda_fp16.h>
#include <cstdint>

// Problem constants
#define B_    4
#define L_    1024
#define FP_   32
#define DP_   8
#define F_    32
#define D_    16
#define K_    3
#define W_    1022            // L - K + 1
#define N_    96              // K * FP
#define WB_   4088            // W * B
#define COLS_ 512             // F * D
#define UH_PER_WB 49152       // N * COLS
#define ITERS_ 3
#define GRID_ 148             // persistent CTAs

// Global scratch for u_hat in fp16: 4088 * 49152 * 2B = 401.8 MB
__device__ __half g_uhat[(size_t)WB_ * UH_PER_WB];

// ---------------------------------------------------------------------------
// Phase 1: u_hat[wb, n, col] = bias[n,col] + sum_d x[b,w+k,fp,d] * W[n,f,d,e]
// Grid (n=96, tile=32), 256 threads; 2 cols/thread, row-pairs via fma.rn.f32x2.
// ---------------------------------------------------------------------------
__global__ __launch_bounds__(256) void uhat_kernel(const float* __restrict__ x,
                                                   const float* __restrict__ wgt,
                                                   const float* __restrict__ bias)
{
    const int n    = blockIdx.x;      // 0..95
    const int tile = blockIdx.y;      // 0..31
    const int t    = threadIdx.x;
    const int k    = n >> 5;
    const int fp   = n & 31;

    __shared__ float xsT[DP_][128];   // transposed: xsT[d][r]

    {
        int r = t >> 1, q = t & 1;
        int wb = tile * 128 + r;
        float4 v = make_float4(0.f, 0.f, 0.f, 0.f);
        if (wb < WB_) {
            int w = wb >> 2, b = wb & 3;
            const float* p = x + ((size_t)b * (L_ * FP_ * DP_)
                                  + (size_t)(w + k) * (FP_ * DP_)
                                  + fp * DP_ + q * 4);
            v = *(const float4*)p;
        }
        xsT[q * 4 + 0][r] = v.x;
        xsT[q * 4 + 1][r] = v.y;
        xsT[q * 4 + 2][r] = v.z;
        xsT[q * 4 + 3][r] = v.w;
    }

    const int c0 = 2 * t;
    const int f  = c0 >> 4;
    const int e0 = c0 & 15;
    unsigned long long wd0[DP_], wd1[DP_];
    const float* wp = wgt + (size_t)n * (F_ * DP_ * D_) + f * (DP_ * D_) + e0;
#pragma unroll
    for (int d = 0; d < DP_; d++) {
        float2 w2 = *(const float2*)(wp + d * D_);
        asm("mov.b64 %0, {%1, %1};" : "=l"(wd0[d]) : "f"(w2.x));
        asm("mov.b64 %0, {%1, %1};" : "=l"(wd1[d]) : "f"(w2.y));
    }
    float2 bz = *(const float2*)(bias + (size_t)n * COLS_ + c0);
    unsigned long long bia, bib;
    asm("mov.b64 %0, {%1, %1};" : "=l"(bia) : "f"(bz.x));
    asm("mov.b64 %0, {%1, %1};" : "=l"(bib) : "f"(bz.y));

    __syncthreads();

    const int wb0 = tile * 128;
#pragma unroll 1
    for (int r = 0; r < 128; r += 2) {
        unsigned long long acc0 = bia, acc1 = bib;
#pragma unroll
        for (int d = 0; d < DP_; d++) {
            unsigned long long xp = *(const unsigned long long*)&xsT[d][r];
            asm("fma.rn.f32x2 %0, %1, %2, %0;" : "+l"(acc0) : "l"(xp), "l"(wd0[d]));
            asm("fma.rn.f32x2 %0, %1, %2, %0;" : "+l"(acc1) : "l"(xp), "l"(wd1[d]));
        }
        float lo0, hi0, lo1, hi1;
        asm("mov.b64 {%0, %1}, %2;" : "=f"(lo0), "=f"(hi0) : "l"(acc0));
        asm("mov.b64 {%0, %1}, %2;" : "=f"(lo1), "=f"(hi1) : "l"(acc1));
        int wbA = wb0 + r, wbB = wb0 + r + 1;
        if (wbA < WB_)
            *(__half2*)&g_uhat[(size_t)wbA * UH_PER_WB + (size_t)n * COLS_ + c0]
                = __floats2half2_rn(lo0, lo1);
        if (wbB < WB_)
            *(__half2*)&g_uhat[(size_t)wbB * UH_PER_WB + (size_t)n * COLS_ + c0]
                = __floats2half2_rn(hi0, hi1);
    }
}

// ---------------------------------------------------------------------------
// Phase 2: persistent routing. 148 CTAs x 1024 threads; double-buffered fp16
// tile via cp.async. Squash norm fused into the reduce; scale folded into
// consumers; sb zeroing elided (Pass D it=0 writes with '=').
// smem layout (bytes):
//   su0[98304] | su1[98304] | sb f32[12288] | sc f16[6144] | sv f32[2048]
//   | sp f32[8192] | ss f32[128]  => 225408 B
// ---------------------------------------------------------------------------
#define OFF_SU0  0
#define OFF_SU1  98304
#define OFF_SB   196608
#define OFF_SC   208896
#define OFF_SV   215040
#define OFF_SP   217088
#define OFF_SS   225280
#define SMEM_TOTAL 225408

// 1024 threads x 16B x LOAD_ITERS = 98304 bytes per tile
#define LOAD_ITERS 6

__global__ __launch_bounds__(1024, 1) void routing_kernel(float* __restrict__ out)
{
    extern __shared__ __align__(16) unsigned char smem[];
    float*  sb = (float*)(smem + OFF_SB);
    __half* sc = (__half*)(smem + OFF_SC);
    float*  sv = (float*)(smem + OFF_SV);
    float*  sp = (float*)(smem + OFF_SP);
    float*  ss = (float*)(smem + OFF_SS);

    const int t   = threadIdx.x;
    const int bid = blockIdx.x;
    const uint32_t smem_u32 = (uint32_t)__cvta_generic_to_shared(smem);

    // issue cp.async loads for one tile: 6 x (1024 threads x 16B) = 98304 B
    auto issue_load = [&](int wb, int bufsel) {
        const char* src = (const char*)(g_uhat + (size_t)wb * UH_PER_WB) + t * 16;
        uint32_t dst = smem_u32 + (bufsel ? OFF_SU1 : OFF_SU0) + t * 16;
#pragma unroll
        for (int i = 0; i < LOAD_ITERS; i++) {
            asm volatile("cp.async.cg.shared.global [%0], [%1], 16;"
                         :: "r"(dst + i * 16384), "l"(src + (size_t)i * 16384));
        }
        asm volatile("cp.async.commit_group;");
    };

    issue_load(bid, 0);
    int buf = 0;

    // static per-thread mappings
    const int c2   = t & 255;      // col-pair for Pass A
    const int nbegA = (t >> 8) * 24;
    const int l    = t & 31, wrp = t >> 5;
    const int e4   = l & 3;
    const int fD   = (wrp & 3) * 8 + (l >> 2);
    const int n0D  = (wrp >> 2) * 12;
    const int fA   = c2 >> 3;

    for (int wb = bid; wb < WB_; wb += GRID_) {
        const int nxt = wb + GRID_;
        if (nxt < WB_) {
            issue_load(nxt, buf ^ 1);
            asm volatile("cp.async.wait_group 1;" ::: "memory");
        } else {
            asm volatile("cp.async.wait_group 0;" ::: "memory");
        }
        __syncthreads();

        const __half2* su2 = (const __half2*)(smem + (buf ? OFF_SU1 : OFF_SU0));
        const __half*  suh = (const __half*)(smem + (buf ? OFF_SU1 : OFF_SU0));

        for (int it = 0; it < ITERS_; it++) {
            // ---- Pass A: partial s[col] over 24 n per thread
            float ax = 0.f, ay = 0.f;
            if (it == 0) {
#pragma unroll 6
                for (int nn = nbegA; nn < nbegA + 24; nn++) {
                    float2 u = __half22float2(su2[nn * 256 + c2]);
                    ax += u.x; ay += u.y;
                }
            } else {
#pragma unroll 6
                for (int nn = nbegA; nn < nbegA + 24; nn++) {
                    float c = __half2float(sc[nn * 32 + fA]);
                    float2 u = __half22float2(su2[nn * 256 + c2]);
                    ax = fmaf(c, u.x, ax);
                    ay = fmaf(c, u.y, ay);
                }
            }
            ((float2*)sp)[t] = make_float2(ax, ay);
            __syncthreads();

            // ---- fused reduce + squash-norm (warps 0..7)
            if (t < 256) {
                float2 a0 = ((float2*)sp)[t];
                float2 a1 = ((float2*)sp)[t + 256];
                float2 a2 = ((float2*)sp)[t + 512];
                float2 a3 = ((float2*)sp)[t + 768];
                float sx = a0.x + a1.x + a2.x + a3.x;
                float sy = a0.y + a1.y + a2.y + a3.y;
                if (it == 0) { sx *= (1.f / 32.f); sy *= (1.f / 32.f); }
                ((float2*)sv)[t] = make_float2(sx, sy);
                // cols of one f (16 cols = 8 col-pairs) live in 8 adjacent lanes
                float nrm = sx * sx + sy * sy;
                nrm += __shfl_xor_sync(0xffffffffu, nrm, 1);
                nrm += __shfl_xor_sync(0xffffffffu, nrm, 2);
                nrm += __shfl_xor_sync(0xffffffffu, nrm, 4);
                if ((t & 7) == 0) {
                    nrm = fmaxf(nrm, 1e-30f);
                    ss[t >> 3] = nrm / (1.f + nrm) * rsqrtf(nrm);
                }
            }
            __syncthreads();

            if (it < ITERS_ - 1) {
                // ---- Pass D: b[n,f] (=/+=) sum_e (ss[f]*s[f,e]) * u[n,f,e]
                float sf = ss[fD];
                float4 v4 = ((const float4*)sv)[fD * 4 + e4];
                v4.x *= sf; v4.y *= sf; v4.z *= sf; v4.w *= sf;
#pragma unroll 4
                for (int nn = n0D; nn < n0D + 12; nn++) {
                    uint2 raw = *(const uint2*)(suh + nn * 512 + fD * 16 + e4 * 4);
                    float2 u0 = __half22float2(*(__half2*)&raw.x);
                    float2 u1 = __half22float2(*(__half2*)&raw.y);
                    float p = v4.x * u0.x + v4.y * u0.y + v4.z * u1.x + v4.w * u1.y;
                    p += __shfl_down_sync(0xffffffffu, p, 2);
                    p += __shfl_down_sync(0xffffffffu, p, 1);
                    if (e4 == 0) {
                        if (it == 0) sb[nn * 32 + fD] = p;
                        else         sb[nn * 32 + fD] += p;
                    }
                }
                __syncthreads();
                // ---- softmax over f per n -> sc (32 warps x 3 rows)
#pragma unroll
                for (int q = 0; q < 3; q++) {
                    int n = wrp * 3 + q;
                    float b = sb[n * 32 + l];
                    float mx = b;
#pragma unroll
                    for (int o = 16; o > 0; o >>= 1)
                        mx = fmaxf(mx, __shfl_xor_sync(0xffffffffu, mx, o));
                    float e = __expf(b - mx);
                    float z = e;
#pragma unroll
                    for (int o = 16; o > 0; o >>= 1)
                        z += __shfl_xor_sync(0xffffffffu, z, o);
                    sc[n * 32 + l] = __float2half(e / z);
                }
                __syncthreads();
            }
        }

        // ---- output: out[b, w, f, e] = ss[f] * s[f,e]
        if (t < 128) {
            int w = wb >> 2, b = wb & 3;
            float s = ss[t >> 2];
            float4 a = ((float4*)sv)[t];
            a.x *= s; a.y *= s; a.z *= s; a.w *= s;
            ((float4*)(out + (size_t)b * (W_ * COLS_) + (size_t)w * COLS_))[t] = a;
        }
        __syncthreads();
        buf ^= 1;
    }
}

// ---------------------------------------------------------------------------
extern "C" void kernel_launch(void* const* d_in, const int* in_sizes, int n_in,
                              void* d_out, int out_size)
{
    const float* x    = (const float*)d_in[0];
    const float* wgt  = (const float*)d_in[1];
    const float* bias = (const float*)d_in[2];
    float* out = (float*)d_out;

    cudaFuncSetAttribute(routing_kernel,
                         cudaFuncAttributeMaxDynamicSharedMemorySize, SMEM_TOTAL);

    dim3 g1(N_, 32);
    uhat_kernel<<<g1, 256>>>(x, wgt, bias);
    routing_kernel<<<GRID_, 1024, SMEM_TOTAL>>>(out);
}

// round 5
// speedup vs baseline: 2.2776x; 1.1190x over previous
#include <cuda_runtime.h>
#include <cuda_fp16.h>
#include <cstdint>

// Problem constants
#define B_    4
#define L_    1024
#define FP_   32
#define DP_   8
#define F_    32
#define D_    16
#define K_    3
#define W_    1022            // L - K + 1
#define N_    96              // K * FP
#define WB_   4088            // W * B
#define COLS_ 512             // F * D
#define UH_PER_WB 49152       // N * COLS
#define ITERS_ 3
#define GRID_ 148             // persistent CTAs

// Global scratch for u_hat in fp16: 4088 * 49152 * 2B = 401.8 MB
__device__ __half g_uhat[(size_t)WB_ * UH_PER_WB];

// ---------------------------------------------------------------------------
// Phase 1: u_hat[wb, n, col] = bias[n,col] + sum_d x[b,w+k,fp,d] * W[n,f,d,e]
// Grid (n=96, tile=32), 256 threads; 2 cols/thread, row-pairs via fma.rn.f32x2.
// ---------------------------------------------------------------------------
__global__ __launch_bounds__(256) void uhat_kernel(const float* __restrict__ x,
                                                   const float* __restrict__ wgt,
                                                   const float* __restrict__ bias)
{
    const int n    = blockIdx.x;      // 0..95
    const int tile = blockIdx.y;      // 0..31
    const int t    = threadIdx.x;
    const int k    = n >> 5;
    const int fp   = n & 31;

    __shared__ float xsT[DP_][128];   // transposed: xsT[d][r]

    {
        int r = t >> 1, q = t & 1;
        int wb = tile * 128 + r;
        float4 v = make_float4(0.f, 0.f, 0.f, 0.f);
        if (wb < WB_) {
            int w = wb >> 2, b = wb & 3;
            const float* p = x + ((size_t)b * (L_ * FP_ * DP_)
                                  + (size_t)(w + k) * (FP_ * DP_)
                                  + fp * DP_ + q * 4);
            v = *(const float4*)p;
        }
        xsT[q * 4 + 0][r] = v.x;
        xsT[q * 4 + 1][r] = v.y;
        xsT[q * 4 + 2][r] = v.z;
        xsT[q * 4 + 3][r] = v.w;
    }

    const int c0 = 2 * t;
    const int f  = c0 >> 4;
    const int e0 = c0 & 15;
    unsigned long long wd0[DP_], wd1[DP_];
    const float* wp = wgt + (size_t)n * (F_ * DP_ * D_) + f * (DP_ * D_) + e0;
#pragma unroll
    for (int d = 0; d < DP_; d++) {
        float2 w2 = *(const float2*)(wp + d * D_);
        asm("mov.b64 %0, {%1, %1};" : "=l"(wd0[d]) : "f"(w2.x));
        asm("mov.b64 %0, {%1, %1};" : "=l"(wd1[d]) : "f"(w2.y));
    }
    float2 bz = *(const float2*)(bias + (size_t)n * COLS_ + c0);
    unsigned long long bia, bib;
    asm("mov.b64 %0, {%1, %1};" : "=l"(bia) : "f"(bz.x));
    asm("mov.b64 %0, {%1, %1};" : "=l"(bib) : "f"(bz.y));

    __syncthreads();

    const int wb0 = tile * 128;
#pragma unroll 1
    for (int r = 0; r < 128; r += 2) {
        unsigned long long acc0 = bia, acc1 = bib;
#pragma unroll
        for (int d = 0; d < DP_; d++) {
            unsigned long long xp = *(const unsigned long long*)&xsT[d][r];
            asm("fma.rn.f32x2 %0, %1, %2, %0;" : "+l"(acc0) : "l"(xp), "l"(wd0[d]));
            asm("fma.rn.f32x2 %0, %1, %2, %0;" : "+l"(acc1) : "l"(xp), "l"(wd1[d]));
        }
        float lo0, hi0, lo1, hi1;
        asm("mov.b64 {%0, %1}, %2;" : "=f"(lo0), "=f"(hi0) : "l"(acc0));
        asm("mov.b64 {%0, %1}, %2;" : "=f"(lo1), "=f"(hi1) : "l"(acc1));
        int wbA = wb0 + r, wbB = wb0 + r + 1;
        if (wbA < WB_)
            *(__half2*)&g_uhat[(size_t)wbA * UH_PER_WB + (size_t)n * COLS_ + c0]
                = __floats2half2_rn(lo0, lo1);
        if (wbB < WB_)
            *(__half2*)&g_uhat[(size_t)wbB * UH_PER_WB + (size_t)n * COLS_ + c0]
                = __floats2half2_rn(hi0, hi1);
    }
}

// ---------------------------------------------------------------------------
// Phase 2: persistent routing. 148 CTAs x 1024 threads, double-buffered fp16
// tile via cp.async.
//  - Pass A: 4 cols/thread (LDS.64), 8-way n split, partials in sp.
//  - Reduce: 128 threads, fused squash-norm, writes sv TRANSPOSED svT[e][f].
//  - Fused Pass D + softmax: warp w owns rows 3w..3w+2, logits in registers,
//    lane=f, no max-subtraction, writes coupling coeffs sc directly.
// smem (bytes): su0[98304] su1[98304] sc[6144] svT[2048] sp[16384] ss[128]
//               = 221312
// ---------------------------------------------------------------------------
#define OFF_SU0  0
#define OFF_SU1  98304
#define OFF_SC   196608
#define OFF_SVT  202752
#define OFF_SP   204800
#define OFF_SS   221184
#define SMEM_TOTAL 221312

// 1024 threads x 16B x LOAD_ITERS = 98304 bytes per tile
#define LOAD_ITERS 6

__global__ __launch_bounds__(1024, 1) void routing_kernel(float* __restrict__ out)
{
    extern __shared__ __align__(16) unsigned char smem[];
    __half* sc  = (__half*)(smem + OFF_SC);
    float*  svT = (float*)(smem + OFF_SVT);   // [16][32] : svT[e*32+f]
    float4* sp4 = (float4*)(smem + OFF_SP);   // [1024]
    float*  ss  = (float*)(smem + OFF_SS);    // [32]

    const int t   = threadIdx.x;
    const int bid = blockIdx.x;
    const uint32_t smem_u32 = (uint32_t)__cvta_generic_to_shared(smem);

    auto issue_load = [&](int wb, int bufsel) {
        const char* src = (const char*)(g_uhat + (size_t)wb * UH_PER_WB) + t * 16;
        uint32_t dst = smem_u32 + (bufsel ? OFF_SU1 : OFF_SU0) + t * 16;
#pragma unroll
        for (int i = 0; i < LOAD_ITERS; i++) {
            asm volatile("cp.async.cg.shared.global [%0], [%1], 16;"
                         :: "r"(dst + i * 16384), "l"(src + (size_t)i * 16384));
        }
        asm volatile("cp.async.commit_group;");
    };

    issue_load(bid, 0);
    int buf = 0;

    // Pass A mapping: col-quad q (cols 4q..4q+3), n segment
    const int q    = t & 127;
    const int nA0  = (t >> 7) * 12;      // 8 segments x 12 n
    const int fq   = q >> 2;
    // fused-D mapping
    const int l    = t & 31, wrp = t >> 5;
    const int row0 = wrp * 3;

    for (int wb = bid; wb < WB_; wb += GRID_) {
        const int nxt = wb + GRID_;
        if (nxt < WB_) {
            issue_load(nxt, buf ^ 1);
            asm volatile("cp.async.wait_group 1;" ::: "memory");
        } else {
            asm volatile("cp.async.wait_group 0;" ::: "memory");
        }
        __syncthreads();

        const __half*  suh = (const __half*)(smem + (buf ? OFF_SU1 : OFF_SU0));
        const uint2*   suq = (const uint2*)suh;      // 8B = 4 cols

        float b0 = 0.f, b1 = 0.f, b2 = 0.f;          // register logits (rows 3w..3w+2)

        for (int it = 0; it < ITERS_; it++) {
            // ---- Pass A: partial s over 12 n per thread, 4 cols each
            float4 acc = make_float4(0.f, 0.f, 0.f, 0.f);
            if (it == 0) {
#pragma unroll
                for (int j = 0; j < 12; j++) {
                    int nn = nA0 + j;
                    uint2 raw = suq[nn * 128 + q];
                    float2 u0 = __half22float2(*(__half2*)&raw.x);
                    float2 u1 = __half22float2(*(__half2*)&raw.y);
                    acc.x += u0.x; acc.y += u0.y; acc.z += u1.x; acc.w += u1.y;
                }
            } else {
#pragma unroll
                for (int j = 0; j < 12; j++) {
                    int nn = nA0 + j;
                    float c = __half2float(sc[nn * 32 + fq]);
                    uint2 raw = suq[nn * 128 + q];
                    float2 u0 = __half22float2(*(__half2*)&raw.x);
                    float2 u1 = __half22float2(*(__half2*)&raw.y);
                    acc.x = fmaf(c, u0.x, acc.x); acc.y = fmaf(c, u0.y, acc.y);
                    acc.z = fmaf(c, u1.x, acc.z); acc.w = fmaf(c, u1.y, acc.w);
                }
            }
            sp4[t] = acc;
            __syncthreads();

            // ---- Reduce (8 segs) + fused squash-norm, write svT
            if (t < 128) {
                float4 a = sp4[t];
#pragma unroll
                for (int s = 1; s < 8; s++) {
                    float4 p = sp4[t + s * 128];
                    a.x += p.x; a.y += p.y; a.z += p.z; a.w += p.w;
                }
                if (it == 0) {
                    a.x *= (1.f / 32.f); a.y *= (1.f / 32.f);
                    a.z *= (1.f / 32.f); a.w *= (1.f / 32.f);
                }
                float nrm = a.x * a.x + a.y * a.y + a.z * a.z + a.w * a.w;
                nrm += __shfl_xor_sync(0xffffffffu, nrm, 1);
                nrm += __shfl_xor_sync(0xffffffffu, nrm, 2);
                int f = t >> 2, e0 = (t & 3) * 4;
                if ((t & 3) == 0) {
                    nrm = fmaxf(nrm, 1e-30f);
                    ss[f] = nrm / (1.f + nrm) * rsqrtf(nrm);
                }
                svT[(e0 + 0) * 32 + f] = a.x;
                svT[(e0 + 1) * 32 + f] = a.y;
                svT[(e0 + 2) * 32 + f] = a.z;
                svT[(e0 + 3) * 32 + f] = a.w;
            }
            __syncthreads();

            if (it < ITERS_ - 1) {
                // ---- Fused Pass D + softmax. lane = f, rows row0..row0+2.
                float sf = ss[l];
                float vv[16];
#pragma unroll
                for (int e = 0; e < 16; e++) vv[e] = svT[e * 32 + l] * sf;

                float pr[3];
#pragma unroll
                for (int r = 0; r < 3; r++) {
                    const uint4* p = (const uint4*)(suh + (row0 + r) * 512 + l * 16);
                    uint4 ua = p[0], ub = p[1];
                    float2 x0 = __half22float2(*(__half2*)&ua.x);
                    float2 x1 = __half22float2(*(__half2*)&ua.y);
                    float2 x2 = __half22float2(*(__half2*)&ua.z);
                    float2 x3 = __half22float2(*(__half2*)&ua.w);
                    float2 x4 = __half22float2(*(__half2*)&ub.x);
                    float2 x5 = __half22float2(*(__half2*)&ub.y);
                    float2 x6 = __half22float2(*(__half2*)&ub.z);
                    float2 x7 = __half22float2(*(__half2*)&ub.w);
                    float d = vv[0] * x0.x + vv[1] * x0.y
                            + vv[2] * x1.x + vv[3] * x1.y
                            + vv[4] * x2.x + vv[5] * x2.y
                            + vv[6] * x3.x + vv[7] * x3.y
                            + vv[8] * x4.x + vv[9] * x4.y
                            + vv[10] * x5.x + vv[11] * x5.y
                            + vv[12] * x6.x + vv[13] * x6.y
                            + vv[14] * x7.x + vv[15] * x7.y;
                    pr[r] = d;
                }
                if (it == 0) { b0 = pr[0]; b1 = pr[1]; b2 = pr[2]; }
                else         { b0 += pr[0]; b1 += pr[1]; b2 += pr[2]; }

                // softmax over f (warp) per row, no max-subtraction (|b| small)
                float e0s = __expf(b0), e1s = __expf(b1), e2s = __expf(b2);
                float z0 = e0s, z1 = e1s, z2 = e2s;
#pragma unroll
                for (int o = 16; o > 0; o >>= 1) {
                    z0 += __shfl_xor_sync(0xffffffffu, z0, o);
                    z1 += __shfl_xor_sync(0xffffffffu, z1, o);
                    z2 += __shfl_xor_sync(0xffffffffu, z2, o);
                }
                sc[(row0 + 0) * 32 + l] = __float2half(e0s / z0);
                sc[(row0 + 1) * 32 + l] = __float2half(e1s / z1);
                sc[(row0 + 2) * 32 + l] = __float2half(e2s / z2);
                __syncthreads();
            }
        }

        // ---- output: out[b, w, f, e] = ss[f] * s[f,e]  (from svT)
        if (t < 128) {
            int w = wb >> 2, b = wb & 3;
            int f = t >> 2, e0 = (t & 3) * 4;
            float s = ss[f];
            float4 a;
            a.x = svT[(e0 + 0) * 32 + f] * s;
            a.y = svT[(e0 + 1) * 32 + f] * s;
            a.z = svT[(e0 + 2) * 32 + f] * s;
            a.w = svT[(e0 + 3) * 32 + f] * s;
            *(float4*)(out + (size_t)b * (W_ * COLS_) + (size_t)w * COLS_
                       + f * 16 + e0) = a;
        }
        __syncthreads();
        buf ^= 1;
    }
}

// ---------------------------------------------------------------------------
extern "C" void kernel_launch(void* const* d_in, const int* in_sizes, int n_in,
                              void* d_out, int out_size)
{
    const float* x    = (const float*)d_in[0];
    const float* wgt  = (const float*)d_in[1];
    const float* bias = (const float*)d_in[2];
    float* out = (float*)d_out;

    cudaFuncSetAttribute(routing_kernel,
                         cudaFuncAttributeMaxDynamicSharedMemorySize, SMEM_TOTAL);

    dim3 g1(N_, 32);
    uhat_kernel<<<g1, 256>>>(x, wgt, bias);
    routing_kernel<<<GRID_, 1024, SMEM_TOTAL>>>(out);
}

// round 7
// speedup vs baseline: 2.5587x; 1.1234x over previous
#include <cuda_runtime.h>
#include <cuda_fp16.h>
#include <cstdint>

// Problem constants
#define B_    4
#define L_    1024
#define FP_   32
#define DP_   8
#define F_    32
#define D_    16
#define K_    3
#define W_    1022            // L - K + 1
#define N_    96              // K * FP
#define WB_   4088            // W * B
#define COLS_ 512             // F * D
#define UH_PER_WB 49152       // N * COLS
#define GRID_ 148             // persistent CTAs

// Global scratch for u_hat in fp16: 4088 * 49152 * 2B = 401.8 MB
__device__ __half g_uhat[(size_t)WB_ * UH_PER_WB];

// ---------------------------------------------------------------------------
// Phase 1: u_hat[wb, n, col] = bias[n,col] + sum_d x[b,w+k,fp,d] * W[n,f,d,e]
// Grid (n=96, tile=32), 256 threads; 2 cols/thread, row-pairs via fma.rn.f32x2.
// ---------------------------------------------------------------------------
__global__ __launch_bounds__(256) void uhat_kernel(const float* __restrict__ x,
                                                   const float* __restrict__ wgt,
                                                   const float* __restrict__ bias)
{
    const int n    = blockIdx.x;      // 0..95
    const int tile = blockIdx.y;      // 0..31
    const int t    = threadIdx.x;
    const int k    = n >> 5;
    const int fp   = n & 31;

    __shared__ float xsT[DP_][128];   // transposed: xsT[d][r]

    {
        int r = t >> 1, q = t & 1;
        int wb = tile * 128 + r;
        float4 v = make_float4(0.f, 0.f, 0.f, 0.f);
        if (wb < WB_) {
            int w = wb >> 2, b = wb & 3;
            const float* p = x + ((size_t)b * (L_ * FP_ * DP_)
                                  + (size_t)(w + k) * (FP_ * DP_)
                                  + fp * DP_ + q * 4);
            v = *(const float4*)p;
        }
        xsT[q * 4 + 0][r] = v.x;
        xsT[q * 4 + 1][r] = v.y;
        xsT[q * 4 + 2][r] = v.z;
        xsT[q * 4 + 3][r] = v.w;
    }

    const int c0 = 2 * t;
    const int f  = c0 >> 4;
    const int e0 = c0 & 15;
    unsigned long long wd0[DP_], wd1[DP_];
    const float* wp = wgt + (size_t)n * (F_ * DP_ * D_) + f * (DP_ * D_) + e0;
#pragma unroll
    for (int d = 0; d < DP_; d++) {
        float2 w2 = *(const float2*)(wp + d * D_);
        asm("mov.b64 %0, {%1, %1};" : "=l"(wd0[d]) : "f"(w2.x));
        asm("mov.b64 %0, {%1, %1};" : "=l"(wd1[d]) : "f"(w2.y));
    }
    float2 bz = *(const float2*)(bias + (size_t)n * COLS_ + c0);
    unsigned long long bia, bib;
    asm("mov.b64 %0, {%1, %1};" : "=l"(bia) : "f"(bz.x));
    asm("mov.b64 %0, {%1, %1};" : "=l"(bib) : "f"(bz.y));

    __syncthreads();

    const int wb0 = tile * 128;
#pragma unroll 1
    for (int r = 0; r < 128; r += 2) {
        unsigned long long acc0 = bia, acc1 = bib;
#pragma unroll
        for (int d = 0; d < DP_; d++) {
            unsigned long long xp = *(const unsigned long long*)&xsT[d][r];
            asm("fma.rn.f32x2 %0, %1, %2, %0;" : "+l"(acc0) : "l"(xp), "l"(wd0[d]));
            asm("fma.rn.f32x2 %0, %1, %2, %0;" : "+l"(acc1) : "l"(xp), "l"(wd1[d]));
        }
        float lo0, hi0, lo1, hi1;
        asm("mov.b64 {%0, %1}, %2;" : "=f"(lo0), "=f"(hi0) : "l"(acc0));
        asm("mov.b64 {%0, %1}, %2;" : "=f"(lo1), "=f"(hi1) : "l"(acc1));
        int wbA = wb0 + r, wbB = wb0 + r + 1;
        if (wbA < WB_)
            *(__half2*)&g_uhat[(size_t)wbA * UH_PER_WB + (size_t)n * COLS_ + c0]
                = __floats2half2_rn(lo0, lo1);
        if (wbB < WB_)
            *(__half2*)&g_uhat[(size_t)wbB * UH_PER_WB + (size_t)n * COLS_ + c0]
                = __floats2half2_rn(hi0, hi1);
    }
}

// ---------------------------------------------------------------------------
// Phase 2: persistent routing, 148 CTAs x 1024 threads, double-buffered fp16
// tile via cp.async. 3 smem traversals per tile:
//   init: uniform-c sum -> s0 -> v0 (128-thread reduce + fused squash-norm)
//   round r (x2): ONE traversal fusing logit-dot + register b update +
//     warp softmax + partial-s accumulation; fp16 partials reduced by
//     256 threads (one half2 each); tiny 1-warp squash-norm.
// smem (bytes): su0[98304] su1[98304] spart[32768] svT[2048] ss[128] = 231552
// ---------------------------------------------------------------------------
#define OFF_SU0   0
#define OFF_SU1   98304
#define OFF_SPART 196608
#define OFF_SVT   229376
#define OFF_SS    231424
#define SMEM_TOTAL 231552

// 1024 threads x 16B x LOAD_ITERS = 98304 bytes per tile
#define LOAD_ITERS 6

__global__ __launch_bounds__(1024, 1) void routing_kernel(float* __restrict__ out)
{
    extern __shared__ __align__(16) unsigned char smem[];
    float*   svT = (float*)(smem + OFF_SVT);     // [16][32] : svT[e*32+f] (raw s)
    float*   ss  = (float*)(smem + OFF_SS);      // [32] squash scale per f
    float4*  sp4 = (float4*)(smem + OFF_SPART);  // init staging (16KB of 32KB)
    __half2* sph = (__half2*)(smem + OFF_SPART); // round partials [32][8][32] half2

    const int t   = threadIdx.x;
    const int bid = blockIdx.x;
    const uint32_t smem_u32 = (uint32_t)__cvta_generic_to_shared(smem);

    auto issue_load = [&](int wb, int bufsel) {
        const char* src = (const char*)(g_uhat + (size_t)wb * UH_PER_WB) + t * 16;
        uint32_t dst = smem_u32 + (bufsel ? OFF_SU1 : OFF_SU0) + t * 16;
#pragma unroll
        for (int i = 0; i < LOAD_ITERS; i++) {
            asm volatile("cp.async.cg.shared.global [%0], [%1], 16;"
                         :: "r"(dst + i * 16384), "l"(src + (size_t)i * 16384));
        }
        asm volatile("cp.async.commit_group;");
    };

    issue_load(bid, 0);
    int buf = 0;

    // init-pass mapping: col-quad q (cols 4q..4q+3), 8-way n split
    const int q   = t & 127;
    const int nA0 = (t >> 7) * 12;
    // fused-round mapping
    const int l    = t & 31, wrp = t >> 5;
    const int row0 = wrp * 3;
    // round-reduce mapping (t < 256): one half2 (2 e-values) per thread
    const int fR  = t & 31, e2R = t >> 5;   // e2R in [0,8) when t<256

    for (int wb = bid; wb < WB_; wb += GRID_) {
        const int nxt = wb + GRID_;
        if (nxt < WB_) {
            issue_load(nxt, buf ^ 1);
            asm volatile("cp.async.wait_group 1;" ::: "memory");
        } else {
            asm volatile("cp.async.wait_group 0;" ::: "memory");
        }
        __syncthreads();

        const __half* suh = (const __half*)(smem + (buf ? OFF_SU1 : OFF_SU0));
        const uint2*  suq = (const uint2*)suh;

        // ============ init: s0 = (1/32) * sum_n u ============
        {
            float4 acc = make_float4(0.f, 0.f, 0.f, 0.f);
#pragma unroll
            for (int j = 0; j < 12; j++) {
                int nn = nA0 + j;
                uint2 raw = suq[nn * 128 + q];
                float2 u0 = __half22float2(*(__half2*)&raw.x);
                float2 u1 = __half22float2(*(__half2*)&raw.y);
                acc.x += u0.x; acc.y += u0.y; acc.z += u1.x; acc.w += u1.y;
            }
            sp4[t] = acc;
        }
        __syncthreads();
        if (t < 128) {
            float4 a = sp4[t];
#pragma unroll
            for (int s = 1; s < 8; s++) {
                float4 p = sp4[t + s * 128];
                a.x += p.x; a.y += p.y; a.z += p.z; a.w += p.w;
            }
            a.x *= (1.f / 32.f); a.y *= (1.f / 32.f);
            a.z *= (1.f / 32.f); a.w *= (1.f / 32.f);
            float nrm = a.x * a.x + a.y * a.y + a.z * a.z + a.w * a.w;
            nrm += __shfl_xor_sync(0xffffffffu, nrm, 1);
            nrm += __shfl_xor_sync(0xffffffffu, nrm, 2);
            int f = t >> 2, e0 = (t & 3) * 4;
            if ((t & 3) == 0) {
                nrm = fmaxf(nrm, 1e-30f);
                ss[f] = nrm / (1.f + nrm) * rsqrtf(nrm);
            }
            svT[(e0 + 0) * 32 + f] = a.x;
            svT[(e0 + 1) * 32 + f] = a.y;
            svT[(e0 + 2) * 32 + f] = a.z;
            svT[(e0 + 3) * 32 + f] = a.w;
        }
        __syncthreads();

        // ============ 2 fused rounds ============
        float b0 = 0.f, b1 = 0.f, b2 = 0.f;   // register logits for rows row0..row0+2
#pragma unroll
        for (int rd = 0; rd < 2; rd++) {
            // read current raw s and scale (all warps; lane = f)
            float vvv[16];
#pragma unroll
            for (int e = 0; e < 16; e++) vvv[e] = svT[e * 32 + l];
            float sf = ss[l];

            float sacc[16];
#pragma unroll
            for (int e = 0; e < 16; e++) sacc[e] = 0.f;

#pragma unroll
            for (int r = 0; r < 3; r++) {
                const uint4* p = (const uint4*)(suh + (row0 + r) * 512 + l * 16);
                uint4 ua = p[0], ub = p[1];
                float xx[16];
                *(float2*)&xx[0]  = __half22float2(*(__half2*)&ua.x);
                *(float2*)&xx[2]  = __half22float2(*(__half2*)&ua.y);
                *(float2*)&xx[4]  = __half22float2(*(__half2*)&ua.z);
                *(float2*)&xx[6]  = __half22float2(*(__half2*)&ua.w);
                *(float2*)&xx[8]  = __half22float2(*(__half2*)&ub.x);
                *(float2*)&xx[10] = __half22float2(*(__half2*)&ub.y);
                *(float2*)&xx[12] = __half22float2(*(__half2*)&ub.z);
                *(float2*)&xx[14] = __half22float2(*(__half2*)&ub.w);
                float d = 0.f;
#pragma unroll
                for (int e = 0; e < 16; e++) d = fmaf(vvv[e], xx[e], d);
                float bcur;
                if (r == 0)      { b0 = fmaf(sf, d, b0); bcur = b0; }
                else if (r == 1) { b1 = fmaf(sf, d, b1); bcur = b1; }
                else             { b2 = fmaf(sf, d, b2); bcur = b2; }
                // warp softmax over f (no max-subtraction: |b| small)
                float ex = __expf(bcur);
                float z = ex;
#pragma unroll
                for (int o = 16; o > 0; o >>= 1)
                    z += __shfl_xor_sync(0xffffffffu, z, o);
                float c = __fdividef(ex, z);
#pragma unroll
                for (int e = 0; e < 16; e++) sacc[e] = fmaf(c, xx[e], sacc[e]);
            }
            // store fp16 partials: sph[warp][e2][f]
#pragma unroll
            for (int e2 = 0; e2 < 8; e2++)
                sph[wrp * 256 + e2 * 32 + l] = __floats2half2_rn(sacc[2 * e2],
                                                                 sacc[2 * e2 + 1]);
            __syncthreads();

            // reduce over 32 warps (256 threads: 8 e-pairs x 32 f), write raw s
            if (t < 256) {
                float sx = 0.f, sy = 0.f;
#pragma unroll
                for (int w2 = 0; w2 < 32; w2++) {
                    float2 u = __half22float2(sph[w2 * 256 + e2R * 32 + fR]);
                    sx += u.x; sy += u.y;
                }
                svT[(2 * e2R) * 32 + fR]     = sx;
                svT[(2 * e2R + 1) * 32 + fR] = sy;
            }
            __syncthreads();
            // squash-norm (1 warp)
            if (t < 32) {
                float nrm = 0.f;
#pragma unroll
                for (int e = 0; e < 16; e++) {
                    float v = svT[e * 32 + t];
                    nrm = fmaf(v, v, nrm);
                }
                nrm = fmaxf(nrm, 1e-30f);
                ss[t] = nrm / (1.f + nrm) * rsqrtf(nrm);
            }
            __syncthreads();
        }

        // ============ output: out[b, w, f, e] = ss[f] * s[f,e] ============
        if (t < 128) {
            int w = wb >> 2, b = wb & 3;
            int f = t >> 2, e0 = (t & 3) * 4;
            float s = ss[f];
            float4 a;
            a.x = svT[(e0 + 0) * 32 + f] * s;
            a.y = svT[(e0 + 1) * 32 + f] * s;
            a.z = svT[(e0 + 2) * 32 + f] * s;
            a.w = svT[(e0 + 3) * 32 + f] * s;
            *(float4*)(out + (size_t)b * (W_ * COLS_) + (size_t)w * COLS_
                       + f * 16 + e0) = a;
        }
        __syncthreads();
        buf ^= 1;
    }
}

// ---------------------------------------------------------------------------
extern "C" void kernel_launch(void* const* d_in, const int* in_sizes, int n_in,
                              void* d_out, int out_size)
{
    const float* x    = (const float*)d_in[0];
    const float* wgt  = (const float*)d_in[1];
    const float* bias = (const float*)d_in[2];
    float* out = (float*)d_out;

    cudaFuncSetAttribute(routing_kernel,
                         cudaFuncAttributeMaxDynamicSharedMemorySize, SMEM_TOTAL);

    dim3 g1(N_, 32);
    uhat_kernel<<<g1, 256>>>(x, wgt, bias);
    routing_kernel<<<GRID_, 1024, SMEM_TOTAL>>>(out);
}